// round 1
// baseline (speedup 1.0000x reference)
#include <cuda_runtime.h>
#include <cuda_fp16.h>
#include <cstdint>

// Problem constants
#define B_BATCH  16
#define L_LEN    320000
#define NFFT     2048
#define HOP      512
#define KFREQ    1025          // N_FFT/2 + 1
#define T_FRAMES 626           // (L + 2*1024 - 2048)/512 + 1
#define M_ROWS   (B_BATCH * T_FRAMES)   // 10016
#define KDIM     NFFT          // 2048 (GEMM reduction dim)
#define NOUT     (2 * KFREQ)   // 2050 (real || imag)
#define NPAD     2176          // 17 * 128

// GEMM tiling
#define BM 128
#define BN 128
#define BK 32
#define TPB 256

// Scratch (allocation-free rule: __device__ globals)
__device__ __half g_frames[(size_t)M_ROWS * KDIM];   // ~41 MB
__device__ __half g_w[(size_t)KDIM * NPAD];          // ~8.9 MB

// ---------------------------------------------------------------------------
// Prep: pack W_real || W_imag into fp16, padded columns zeroed
// ---------------------------------------------------------------------------
__global__ void prep_w_kernel(const float* __restrict__ wr,
                              const float* __restrict__ wi) {
    int idx = blockIdx.x * blockDim.x + threadIdx.x;
    const int total = KDIM * NPAD;
    if (idx >= total) return;
    int r = idx / NPAD;
    int c = idx - r * NPAD;
    float v = 0.0f;
    if (c < KFREQ)      v = wr[(size_t)r * KFREQ + c];
    else if (c < NOUT)  v = wi[(size_t)r * KFREQ + (c - KFREQ)];
    g_w[idx] = __float2half(v);
}

// ---------------------------------------------------------------------------
// Prep: materialize reflect-padded frames as fp16 (one thread = 8 halves)
// ---------------------------------------------------------------------------
__global__ void prep_frames_kernel(const float* __restrict__ x) {
    int idx = blockIdx.x * blockDim.x + threadIdx.x;   // 8-half group id
    int m = idx >> 8;                                  // 2048/8 = 256 groups/row
    if (m >= M_ROWS) return;
    int c8 = (idx & 255) << 3;
    int b = m / T_FRAMES;
    int t = m - b * T_FRAMES;
    const float* xb = x + (size_t)b * L_LEN;
    int j0 = t * HOP + c8 - 1024;                      // index into x (pre-pad)
    __half h[8];
#pragma unroll
    for (int j = 0; j < 8; j++) {
        int jj = j0 + j;
        if (jj < 0)            jj = -jj;               // reflect left
        else if (jj >= L_LEN)  jj = 2 * (L_LEN - 1) - jj;  // reflect right
        h[j] = __float2half(xb[jj]);
    }
    *reinterpret_cast<uint4*>(&g_frames[(size_t)m * KDIM + c8]) =
        *reinterpret_cast<uint4*>(h);
}

// ---------------------------------------------------------------------------
// PTX helpers
// ---------------------------------------------------------------------------
__device__ __forceinline__ void ldsm_x4(uint32_t& r0, uint32_t& r1,
                                        uint32_t& r2, uint32_t& r3,
                                        const void* p) {
    uint32_t addr = (uint32_t)__cvta_generic_to_shared(p);
    asm volatile("ldmatrix.sync.aligned.m8n8.x4.shared.b16 {%0,%1,%2,%3}, [%4];\n"
                 : "=r"(r0), "=r"(r1), "=r"(r2), "=r"(r3) : "r"(addr));
}

__device__ __forceinline__ void ldsm_x4_trans(uint32_t& r0, uint32_t& r1,
                                              uint32_t& r2, uint32_t& r3,
                                              const void* p) {
    uint32_t addr = (uint32_t)__cvta_generic_to_shared(p);
    asm volatile("ldmatrix.sync.aligned.m8n8.x4.trans.shared.b16 {%0,%1,%2,%3}, [%4];\n"
                 : "=r"(r0), "=r"(r1), "=r"(r2), "=r"(r3) : "r"(addr));
}

__device__ __forceinline__ void mma16816(float* d, const uint32_t* a,
                                         const uint32_t* b) {
    asm volatile(
        "mma.sync.aligned.m16n8k16.row.col.f32.f16.f16.f32 "
        "{%0,%1,%2,%3}, {%4,%5,%6,%7}, {%8,%9}, {%0,%1,%2,%3};\n"
        : "+f"(d[0]), "+f"(d[1]), "+f"(d[2]), "+f"(d[3])
        : "r"(a[0]), "r"(a[1]), "r"(a[2]), "r"(a[3]), "r"(b[0]), "r"(b[1]));
}

// ---------------------------------------------------------------------------
// GEMM: out[M, NOUT] = frames[M, K] @ W[K, NPAD]; split write real/imag
// ---------------------------------------------------------------------------
__global__ __launch_bounds__(TPB, 2)
void gemm_stft_kernel(float* __restrict__ out) {
    __shared__ __half As[BM][BK + 8];   // row stride 80B  -> conflict-free ldmatrix
    __shared__ __half Bs[BK][BN + 8];   // row stride 272B -> conflict-free ldmatrix

    const int bm = blockIdx.y, bn = blockIdx.x;
    const int tid = threadIdx.x;
    const int wid = tid >> 5, lane = tid & 31;
    const int wm = wid >> 1;            // 0..3  (32 rows each)
    const int wn = wid & 1;             // 0..1  (64 cols each)

    float acc[2][8][4];
#pragma unroll
    for (int i = 0; i < 2; i++)
#pragma unroll
        for (int j = 0; j < 8; j++)
#pragma unroll
            for (int q = 0; q < 4; q++) acc[i][j][q] = 0.0f;

    const __half* __restrict__ Ag = g_frames;
    const __half* __restrict__ Bg = g_w;

    uint4 aReg[2], bReg[2];

    // ---- global tile load into registers (kt = K-tile index) ----
#define LOAD_A(kt, dst)                                                        \
    {                                                                          \
        _Pragma("unroll")                                                      \
        for (int s = 0; s < 2; s++) {                                          \
            int i = tid + s * TPB;                                             \
            int row = i >> 2, c8 = (i & 3) << 3;                               \
            int grow = bm * BM + row;                                          \
            if (grow < M_ROWS)                                                 \
                dst[s] = *reinterpret_cast<const uint4*>(                      \
                    &Ag[(size_t)grow * KDIM + (kt) * BK + c8]);                \
            else                                                               \
                dst[s] = make_uint4(0u, 0u, 0u, 0u);                           \
        }                                                                      \
    }
#define LOAD_B(kt, dst)                                                        \
    {                                                                          \
        _Pragma("unroll")                                                      \
        for (int s = 0; s < 2; s++) {                                          \
            int i = tid + s * TPB;                                             \
            int row = i >> 4, c8 = (i & 15) << 3;                              \
            dst[s] = *reinterpret_cast<const uint4*>(                          \
                &Bg[(size_t)((kt) * BK + row) * NPAD + bn * BN + c8]);         \
        }                                                                      \
    }
#define STORE_SMEM(asrc, bsrc)                                                 \
    {                                                                          \
        _Pragma("unroll")                                                      \
        for (int s = 0; s < 2; s++) {                                          \
            int i = tid + s * TPB;                                             \
            int row = i >> 2, c8 = (i & 3) << 3;                               \
            *reinterpret_cast<uint4*>(&As[row][c8]) = asrc[s];                 \
        }                                                                      \
        _Pragma("unroll")                                                      \
        for (int s = 0; s < 2; s++) {                                          \
            int i = tid + s * TPB;                                             \
            int row = i >> 4, c8 = (i & 15) << 3;                              \
            *reinterpret_cast<uint4*>(&Bs[row][c8]) = bsrc[s];                 \
        }                                                                      \
    }

    LOAD_A(0, aReg);
    LOAD_B(0, bReg);
    STORE_SMEM(aReg, bReg);
    __syncthreads();

    const int KT = KDIM / BK;   // 64
    for (int kt = 0; kt < KT; kt++) {
        uint4 aN[2], bN[2];
        if (kt + 1 < KT) {
            LOAD_A(kt + 1, aN);
            LOAD_B(kt + 1, bN);
        }

#pragma unroll
        for (int kk = 0; kk < 2; kk++) {
            // A fragments: two 16x16 tiles per warp
            uint32_t af[2][4];
#pragma unroll
            for (int im = 0; im < 2; im++) {
                int r = wm * 32 + im * 16 + (lane & 15);
                int c = kk * 16 + ((lane >> 4) << 3);
                ldsm_x4(af[im][0], af[im][1], af[im][2], af[im][3], &As[r][c]);
            }
            // B fragments: eight 16x8 tiles per warp (4 x ldmatrix.x4.trans)
            uint32_t bf[8][2];
#pragma unroll
            for (int inp = 0; inp < 4; inp++) {
                int krow = kk * 16 + (lane & 7) + (((lane >> 3) & 1) << 3);
                int ncol = wn * 64 + inp * 16 + ((lane >> 4) << 3);
                uint32_t r0, r1, r2, r3;
                ldsm_x4_trans(r0, r1, r2, r3, &Bs[krow][ncol]);
                bf[inp * 2][0] = r0;  bf[inp * 2][1] = r1;
                bf[inp * 2 + 1][0] = r2;  bf[inp * 2 + 1][1] = r3;
            }
#pragma unroll
            for (int im = 0; im < 2; im++)
#pragma unroll
                for (int in = 0; in < 8; in++)
                    mma16816(acc[im][in], af[im], bf[in]);
        }

        if (kt + 1 < KT) {
            __syncthreads();
            STORE_SMEM(aN, bN);
            __syncthreads();
        }
    }

    // ---- epilogue: split into real / imag halves of d_out ----
    const int g = lane >> 2, tq = lane & 3;
    const size_t imag_base = (size_t)M_ROWS * KFREQ;
#pragma unroll
    for (int im = 0; im < 2; im++) {
        int row0 = bm * BM + wm * 32 + im * 16 + g;
#pragma unroll
        for (int in = 0; in < 8; in++) {
            int col0 = bn * BN + wn * 64 + in * 8 + tq * 2;
#pragma unroll
            for (int half = 0; half < 2; half++) {
                int row = row0 + half * 8;
                if (row >= M_ROWS) continue;
#pragma unroll
                for (int e = 0; e < 2; e++) {
                    int col = col0 + e;
                    float v = acc[im][in][half * 2 + e];
                    if (col < KFREQ)
                        out[(size_t)row * KFREQ + col] = v;
                    else if (col < NOUT)
                        out[imag_base + (size_t)row * KFREQ + (col - KFREQ)] = v;
                }
            }
        }
    }
}

// ---------------------------------------------------------------------------
extern "C" void kernel_launch(void* const* d_in, const int* in_sizes, int n_in,
                              void* d_out, int out_size) {
    const float* x  = (const float*)d_in[0];
    const float* wr = (const float*)d_in[1];
    const float* wi = (const float*)d_in[2];
    float* out = (float*)d_out;

    {
        int total = KDIM * NPAD;
        prep_w_kernel<<<(total + 255) / 256, 256>>>(wr, wi);
    }
    {
        int total = M_ROWS * (KDIM / 8);
        prep_frames_kernel<<<(total + 255) / 256, 256>>>(x);
    }
    {
        dim3 grid(NPAD / BN, (M_ROWS + BM - 1) / BM);  // 17 x 79
        gemm_stft_kernel<<<grid, TPB>>>(out);
    }
}

// round 4
// speedup vs baseline: 1.0216x; 1.0216x over previous
#include <cuda_runtime.h>
#include <cuda_fp16.h>
#include <cstdint>

// ---------------------------------------------------------------------------
// Problem constants
// ---------------------------------------------------------------------------
#define B_BATCH  16
#define L_LEN    320000
#define NFFT     2048
#define HOP      512
#define KFREQ    1025                    // N_FFT/2 + 1
#define T_FRAMES 626
#define M_ROWS   (B_BATCH * T_FRAMES)    // 10016
#define KDIM     2048
#define NOUT     (2 * KFREQ)             // 2050
#define NPAD     2176                    // 17 * 128

// GEMM tiling
#define BM       256
#define BN       128
#define BK       64                      // 128 B/row fp16 = one SW128 atom row
#define STAGES   3
#define TPB      256
#define KCHUNKS  (KDIM / BK)             // 32
#define A_STAGE_BYTES (BM * BK * 2)      // 32 KB
#define B_STAGE_BYTES (BN * BK * 2)      // 16 KB
#define STAGE_BYTES   (A_STAGE_BYTES + B_STAGE_BYTES)    // 48 KB
#define SMEM_TOTAL    (STAGES * STAGE_BYTES)             // 147456

// Scratch (__device__ globals: allocation-free rule)
__device__ __half g_frames[(size_t)M_ROWS * KDIM];   // ~41 MB
__device__ __half g_w[(size_t)KDIM * NPAD];          // ~8.9 MB, [k][n]

// ---------------------------------------------------------------------------
// PTX helpers
// ---------------------------------------------------------------------------
__device__ __forceinline__ uint32_t swz128(uint32_t off) {
    return off ^ ((off >> 3) & 0x70);
}
__device__ __forceinline__ void cp16(uint32_t dst, const void* src) {
    asm volatile("cp.async.cg.shared.global [%0], [%1], 16;\n"
                 :: "r"(dst), "l"(src));
}
__device__ __forceinline__ void cp16_pred(uint32_t dst, const void* src, bool ok) {
    // src-size = 0 zero-fills when !ok
    int sz = ok ? 16 : 0;
    asm volatile("cp.async.cg.shared.global [%0], [%1], 16, %2;\n"
                 :: "r"(dst), "l"(src), "r"(sz));
}
__device__ __forceinline__ void cp_commit() {
    asm volatile("cp.async.commit_group;\n" ::: "memory");
}
__device__ __forceinline__ void cp_wait2() {
    asm volatile("cp.async.wait_group 2;\n" ::: "memory");
}
__device__ __forceinline__ void ldsm_x4(uint32_t& r0, uint32_t& r1,
                                        uint32_t& r2, uint32_t& r3,
                                        uint32_t addr) {
    asm volatile("ldmatrix.sync.aligned.m8n8.x4.shared.b16 {%0,%1,%2,%3}, [%4];\n"
                 : "=r"(r0), "=r"(r1), "=r"(r2), "=r"(r3) : "r"(addr));
}
__device__ __forceinline__ void ldsm_x4_trans(uint32_t& r0, uint32_t& r1,
                                              uint32_t& r2, uint32_t& r3,
                                              uint32_t addr) {
    asm volatile("ldmatrix.sync.aligned.m8n8.x4.trans.shared.b16 {%0,%1,%2,%3}, [%4];\n"
                 : "=r"(r0), "=r"(r1), "=r"(r2), "=r"(r3) : "r"(addr));
}
__device__ __forceinline__ void mma16816(float* d, const uint32_t* a,
                                         const uint32_t* b) {
    asm volatile(
        "mma.sync.aligned.m16n8k16.row.col.f32.f16.f16.f32 "
        "{%0,%1,%2,%3}, {%4,%5,%6,%7}, {%8,%9}, {%0,%1,%2,%3};\n"
        : "+f"(d[0]), "+f"(d[1]), "+f"(d[2]), "+f"(d[3])
        : "r"(a[0]), "r"(a[1]), "r"(a[2]), "r"(a[3]), "r"(b[0]), "r"(b[1]));
}

// ---------------------------------------------------------------------------
// Prep: pack W_real || W_imag into fp16 [k][NPAD], padded cols zero (8/thread)
// ---------------------------------------------------------------------------
__global__ void prep_w_kernel(const float* __restrict__ wr,
                              const float* __restrict__ wi) {
    int idx = blockIdx.x * blockDim.x + threadIdx.x;   // one 8-output group
    const int total = KDIM * NPAD / 8;
    if (idx >= total) return;
    int t = idx * 8;
    int k = t / NPAD;
    int n0 = t - k * NPAD;                             // NPAD % 8 == 0 -> same row
    __half h[8];
#pragma unroll
    for (int j = 0; j < 8; j++) {
        int n = n0 + j;
        float v = 0.0f;
        if (n < KFREQ)      v = wr[(size_t)k * KFREQ + n];
        else if (n < NOUT)  v = wi[(size_t)k * KFREQ + (n - KFREQ)];
        h[j] = __float2half(v);
    }
    *reinterpret_cast<uint4*>(&g_w[(size_t)k * NPAD + n0]) =
        *reinterpret_cast<uint4*>(h);
}

// ---------------------------------------------------------------------------
// Prep: reflect-padded frames as fp16 (8 halves / thread)
// ---------------------------------------------------------------------------
__global__ void prep_frames_kernel(const float* __restrict__ x) {
    int idx = blockIdx.x * blockDim.x + threadIdx.x;
    int m = idx >> 8;
    if (m >= M_ROWS) return;
    int c8 = (idx & 255) << 3;
    int b = m / T_FRAMES;
    int t = m - b * T_FRAMES;
    const float* xb = x + (size_t)b * L_LEN;
    int j0 = t * HOP + c8 - 1024;
    __half h[8];
#pragma unroll
    for (int j = 0; j < 8; j++) {
        int jj = j0 + j;
        if (jj < 0)           jj = -jj;
        else if (jj >= L_LEN) jj = 2 * (L_LEN - 1) - jj;
        h[j] = __float2half(xb[jj]);
    }
    *reinterpret_cast<uint4*>(&g_frames[(size_t)m * KDIM + c8]) =
        *reinterpret_cast<uint4*>(h);
}

// ---------------------------------------------------------------------------
// GEMM: out = frames[M,K] @ W[K,NPAD], tiles 256x128, 3-stage cp.async, BK=64
// 8 warps: warp grid 4(m) x 2(n), warp tile 64x64
// ---------------------------------------------------------------------------
__global__ __launch_bounds__(TPB, 1)
void gemm_mma_kernel(float* __restrict__ out) {
    extern __shared__ char smem[];
    const uint32_t sb = (uint32_t)__cvta_generic_to_shared(smem);

    const int tid = threadIdx.x;
    const int wid = tid >> 5, lane = tid & 31;
    const int wm = wid >> 1;           // 0..3 : 64-row group
    const int wn = wid & 1;            // 0..1 : 64-col group (== B subtile)
    const int bm = blockIdx.y, bn = blockIdx.x;

    float acc[4][8][4];
#pragma unroll
    for (int i = 0; i < 4; i++)
#pragma unroll
        for (int j = 0; j < 8; j++)
#pragma unroll
            for (int q = 0; q < 4; q++) acc[i][j][q] = 0.0f;

    // ---- stage loader: K-chunk -> stage s --------------------------------
    auto load_stage = [&](int chunk, int s) {
        const uint32_t abase = sb + s * STAGE_BYTES;
        const uint32_t bbase = abase + A_STAGE_BYTES;
        const int kcol = chunk * BK;
        // A: 256 rows x 128B, SW128. 2048 chunks of 16B -> 8 per thread.
#pragma unroll
        for (int q = 0; q < 8; q++) {
            int i = q * TPB + tid;
            int row = i >> 3, c16 = i & 7;
            uint32_t dst = abase + swz128((uint32_t)(row * 128 + c16 * 16));
            int grow = bm * BM + row;
            int gr = grow < M_ROWS ? grow : 0;
            cp16_pred(dst, &g_frames[(size_t)gr * KDIM + kcol + c16 * 8],
                      grow < M_ROWS);
        }
        // B: 2 subtiles of 64 rows x 128B (64 cols), SW128. 1024 chunks -> 4/thread.
#pragma unroll
        for (int q = 0; q < 4; q++) {
            int i = q * TPB + tid;
            int sub = i >> 9;                  // 0 or 1
            int j = i & 511;
            int krow = j >> 3, c16 = j & 7;
            uint32_t dst = bbase + sub * (BK * 128) +
                           swz128((uint32_t)(krow * 128 + c16 * 16));
            cp16(dst, &g_w[(size_t)(kcol + krow) * NPAD + bn * BN + sub * 64 +
                           c16 * 8]);
        }
    };

    // ---- prologue
    load_stage(0, 0); cp_commit();
    load_stage(1, 1); cp_commit();

    // ---- main loop
    for (int j = 0; j < KCHUNKS; j++) {
        if (j + 2 < KCHUNKS) load_stage(j + 2, (j + 2) % STAGES);
        cp_commit();
        cp_wait2();                   // chunk j resident
        __syncthreads();

        const uint32_t abase = sb + (j % STAGES) * STAGE_BYTES;
        const uint32_t bbase = abase + A_STAGE_BYTES + wn * (BK * 128);

#pragma unroll
        for (int kk = 0; kk < 4; kk++) {
            // A fragments: 4 x m16k16
            uint32_t af[4][4];
#pragma unroll
            for (int im = 0; im < 4; im++) {
                int r = wm * 64 + im * 16 + (lane & 15);
                uint32_t addr = abase +
                    swz128((uint32_t)(r * 128 + kk * 32 + ((lane >> 4) << 4)));
                ldsm_x4(af[im][0], af[im][1], af[im][2], af[im][3], addr);
            }
            // B fragments: 8 x n8k16 via 4 ldsm.trans
            uint32_t bf[8][2];
#pragma unroll
            for (int inp = 0; inp < 4; inp++) {
                int krow = kk * 16 + (lane & 15);
                uint32_t addr = bbase +
                    swz128((uint32_t)(krow * 128 + inp * 32 + ((lane >> 4) << 4)));
                uint32_t r0, r1, r2, r3;
                ldsm_x4_trans(r0, r1, r2, r3, addr);
                bf[inp * 2][0] = r0;      bf[inp * 2][1] = r1;
                bf[inp * 2 + 1][0] = r2;  bf[inp * 2 + 1][1] = r3;
            }
#pragma unroll
            for (int im = 0; im < 4; im++)
#pragma unroll
                for (int in = 0; in < 8; in++)
                    mma16816(acc[im][in], af[im], bf[in]);
        }
        __syncthreads();
    }

    // ---- epilogue: scalar 4B stores (row stride 1025 floats is odd ->
    //      float2 would be 8B-misaligned on odd rows; lanes still coalesce)
    const int g = lane >> 2, tq = lane & 3;
    const size_t imag_base = (size_t)M_ROWS * KFREQ;
#pragma unroll
    for (int im = 0; im < 4; im++) {
#pragma unroll
        for (int in = 0; in < 8; in++) {
            int col0 = bn * BN + wn * 64 + in * 8 + tq * 2;
#pragma unroll
            for (int half = 0; half < 2; half++) {
                int row = bm * BM + wm * 64 + im * 16 + g + half * 8;
                if (row >= M_ROWS) continue;
#pragma unroll
                for (int e = 0; e < 2; e++) {
                    int col = col0 + e;
                    float v = acc[im][in][half * 2 + e];
                    if (col < KFREQ)
                        out[(size_t)row * KFREQ + col] = v;
                    else if (col < NOUT)
                        out[imag_base + (size_t)row * KFREQ + (col - KFREQ)] = v;
                }
            }
        }
    }
}

// ---------------------------------------------------------------------------
extern "C" void kernel_launch(void* const* d_in, const int* in_sizes, int n_in,
                              void* d_out, int out_size) {
    const float* x  = (const float*)d_in[0];
    const float* wr = (const float*)d_in[1];
    const float* wi = (const float*)d_in[2];
    float* out = (float*)d_out;

    {
        int total = KDIM * NPAD / 8;
        prep_w_kernel<<<(total + 255) / 256, 256>>>(wr, wi);
    }
    {
        int total = M_ROWS * (KDIM / 8);
        prep_frames_kernel<<<(total + 255) / 256, 256>>>(x);
    }
    {
        cudaFuncSetAttribute(gemm_mma_kernel,
                             cudaFuncAttributeMaxDynamicSharedMemorySize,
                             SMEM_TOTAL);
        dim3 grid(NPAD / BN, (M_ROWS + BM - 1) / BM);   // 17 x 40
        gemm_mma_kernel<<<grid, TPB, SMEM_TOTAL>>>(out);
    }
}

// round 5
// speedup vs baseline: 1.2103x; 1.1847x over previous
#include <cuda_runtime.h>
#include <cuda_fp16.h>
#include <cstdint>

// ---------------------------------------------------------------------------
// Problem constants
// ---------------------------------------------------------------------------
#define B_BATCH  16
#define L_LEN    320000
#define NFFT     2048
#define HOP      512
#define KFREQ    1025                     // N_FFT/2 + 1
#define T_FRAMES 626
#define M_ROWS   (B_BATCH * T_FRAMES)     // 10016
// Cooley-Tukey factorization: n = n1 + 64*n2, n1 in [0,64), n2 in [0,32)
// Stage 1: Y[m,n1,r] = sum_n2 xw[m, n1+64*n2] * exp(-2pi i n2 r / 32)
// Stage 2: X[m,k]    = sum_n1 Y[m,n1,k&31] * exp(-2pi i n1 k / 2048)
#define M1       (M_ROWS * 64)            // 641024 stage-1 rows
#define S2_NB    72                       // padded stage-2 N (66 used)

// Scratch (__device__ globals — allocation-free rule)
__device__ __half g_a1[(size_t)M1 * 32];              // ~41 MB  [m*64+n1][n2]
__device__ __half g_y [(size_t)M_ROWS * 4096];        // ~82 MB  [m][r][c][n1]
__device__ __half g_b1[32 * 64];                      // [n2][j] j<32:re j>=32:im
__device__ __half g_b2[32 * 128 * S2_NB];             // [r][kk][j]

// ---------------------------------------------------------------------------
// PTX helpers
// ---------------------------------------------------------------------------
__device__ __forceinline__ uint32_t swz128(uint32_t off) {
    return off ^ ((off >> 3) & 0x70);
}
__device__ __forceinline__ void cp16(uint32_t dst, const void* src) {
    asm volatile("cp.async.cg.shared.global [%0], [%1], 16;\n"
                 :: "r"(dst), "l"(src));
}
__device__ __forceinline__ void cp16_pred(uint32_t dst, const void* src, bool ok) {
    int sz = ok ? 16 : 0;
    asm volatile("cp.async.cg.shared.global [%0], [%1], 16, %2;\n"
                 :: "r"(dst), "l"(src), "r"(sz));
}
__device__ __forceinline__ void cp_wait_all() {
    asm volatile("cp.async.commit_group;\n" ::: "memory");
    asm volatile("cp.async.wait_group 0;\n" ::: "memory");
}
__device__ __forceinline__ void ldsm_x4(uint32_t* r, uint32_t addr) {
    asm volatile("ldmatrix.sync.aligned.m8n8.x4.shared.b16 {%0,%1,%2,%3}, [%4];\n"
                 : "=r"(r[0]), "=r"(r[1]), "=r"(r[2]), "=r"(r[3]) : "r"(addr));
}
__device__ __forceinline__ void ldsm_x4_t(uint32_t& r0, uint32_t& r1,
                                          uint32_t& r2, uint32_t& r3,
                                          uint32_t addr) {
    asm volatile("ldmatrix.sync.aligned.m8n8.x4.trans.shared.b16 {%0,%1,%2,%3}, [%4];\n"
                 : "=r"(r0), "=r"(r1), "=r"(r2), "=r"(r3) : "r"(addr));
}
__device__ __forceinline__ void ldsm_x2_t(uint32_t& r0, uint32_t& r1,
                                          uint32_t addr) {
    asm volatile("ldmatrix.sync.aligned.m8n8.x2.trans.shared.b16 {%0,%1}, [%2];\n"
                 : "=r"(r0), "=r"(r1) : "r"(addr));
}
__device__ __forceinline__ void mma16816(float* d, const uint32_t* a,
                                         const uint32_t* b) {
    asm volatile(
        "mma.sync.aligned.m16n8k16.row.col.f32.f16.f16.f32 "
        "{%0,%1,%2,%3}, {%4,%5,%6,%7}, {%8,%9}, {%0,%1,%2,%3};\n"
        : "+f"(d[0]), "+f"(d[1]), "+f"(d[2]), "+f"(d[3])
        : "r"(a[0]), "r"(a[1]), "r"(a[2]), "r"(a[3]), "r"(b[0]), "r"(b[1]));
}

// ---------------------------------------------------------------------------
// Prep: stage-1 DFT32 matrix. B1[n2][j]: j<32 -> cos(2pi n2 j/32),
//                                        j>=32 -> -sin(2pi n2 (j-32)/32)
// ---------------------------------------------------------------------------
__global__ void prep_b1_kernel() {
    int i = blockIdx.x * blockDim.x + threadIdx.x;
    if (i >= 32 * 64) return;
    int n2 = i >> 6, j = i & 63;
    int r = j & 31;
    float s, c;
    sincospif((float)(n2 * r) / 16.0f, &s, &c);
    g_b1[i] = __float2half(j < 32 ? c : -s);
}

// ---------------------------------------------------------------------------
// Prep: stage-2 twiddle*DFT64 matrices.
// B2[r][kk][j]: kk<64 (Y real, n1=kk), kk>=64 (Y imag, n1=kk-64)
//   j = 2*k2 + cout, k = 32*k2 + r, theta = 2pi n1 k / 2048
//   Xre += Yre*cos + Yim*sin ; Xim += -Yre*sin + Yim*cos
// ---------------------------------------------------------------------------
__global__ void prep_b2_kernel() {
    int i = blockIdx.x * blockDim.x + threadIdx.x;
    const int total = 32 * 128 * S2_NB;
    if (i >= total) return;
    int r  = i / (128 * S2_NB);
    int rem = i - r * (128 * S2_NB);
    int kk = rem / S2_NB;
    int j  = rem - kk * S2_NB;
    float v = 0.0f;
    if (j < 66) {
        int n1 = kk & 63;
        int k  = (j >> 1) * 32 + r;
        float s, c;
        sincospif((float)(n1 * k) / 1024.0f, &s, &c);
        bool im_in  = kk >= 64;
        bool im_out = (j & 1) != 0;
        v = im_in ? (im_out ? c : s) : (im_out ? -s : c);
    }
    g_b2[i] = __float2half(v);
}

// ---------------------------------------------------------------------------
// Prep: A1[(m*64+n1)][n2] = window[n1+64*n2] * x_reflectpad[m*512 + n1+64*n2 - 1024]
// One block per frame m; smem transpose 2048 samples -> 64x32.
// ---------------------------------------------------------------------------
__global__ __launch_bounds__(256)
void prep_a1_kernel(const float* __restrict__ x) {
    __shared__ __half st[32 * 72];         // st[n2*72 + n1]
    const int m = blockIdx.x;
    const int tid = threadIdx.x;
    const int b = m / T_FRAMES;
    const int tf = m - b * T_FRAMES;
    const float* xb = x + (size_t)b * L_LEN;
    const int base = tf * HOP - 1024;

#pragma unroll
    for (int i = 0; i < 8; i++) {
        int n = tid * 8 + i;               // 0..2047
        int jj = base + n;
        if (jj < 0)           jj = -jj;
        else if (jj >= L_LEN) jj = 2 * (L_LEN - 1) - jj;
        float w = 0.5f - 0.5f * cospif((float)n / 1024.0f);
        float v = w * xb[jj];
        st[(n >> 6) * 72 + (n & 63)] = __float2half(v);
    }
    __syncthreads();

    // writer: thread -> (n1 = tid>>2, 8 n2 values at (tid&3)*8)
    const int n1 = tid >> 2;
    const int n2q = (tid & 3) * 8;
    __half h[8];
#pragma unroll
    for (int i = 0; i < 8; i++) h[i] = st[(n2q + i) * 72 + n1];
    *reinterpret_cast<uint4*>(&g_a1[((size_t)m * 64 + n1) * 32 + n2q]) =
        *reinterpret_cast<uint4*>(h);
}

// ---------------------------------------------------------------------------
// Stage 1: Y = A1[641024, 32] @ B1[32, 64]   (one-shot tiles, CTA 128x64)
// 4 warps, warp tile 32x64. Output scattered to g_y[m][r][c][n1] fp16.
// ---------------------------------------------------------------------------
__global__ __launch_bounds__(128)
void stage1_kernel() {
    __shared__ __half sA[128 * 32];        // 64B rows, chunk-XOR swizzle
    __shared__ __half sB[32 * 64];         // 128B rows, SW128
    const uint32_t sAb = (uint32_t)__cvta_generic_to_shared(sA);
    const uint32_t sBb = (uint32_t)__cvta_generic_to_shared(sB);
    const int tid = threadIdx.x;
    const int wid = tid >> 5, lane = tid & 31;
    const int bm = blockIdx.x;             // 5008 tiles, exact

    // load A: 512 x 16B
#pragma unroll
    for (int q = 0; q < 4; q++) {
        int i = q * 128 + tid;
        int row = i >> 2, c16 = i & 3;
        int c2 = c16 ^ (row & 3);
        cp16(sAb + row * 64 + c2 * 16,
             &g_a1[((size_t)bm * 128 + row) * 32 + c16 * 8]);
    }
    // load B: 256 x 16B
#pragma unroll
    for (int q = 0; q < 2; q++) {
        int i = q * 128 + tid;
        int row = i >> 3, c8 = i & 7;
        cp16(sBb + swz128((uint32_t)(row * 128 + c8 * 16)),
             &g_b1[row * 64 + c8 * 8]);
    }
    cp_wait_all();
    __syncthreads();

    float acc[2][8][4];
#pragma unroll
    for (int a = 0; a < 2; a++)
#pragma unroll
        for (int bb = 0; bb < 8; bb++)
#pragma unroll
            for (int q = 0; q < 4; q++) acc[a][bb][q] = 0.0f;

#pragma unroll
    for (int ks = 0; ks < 2; ks++) {
        uint32_t af[2][4];
#pragma unroll
        for (int im = 0; im < 2; im++) {
            int row = wid * 32 + im * 16 + (lane & 15);
            int c2 = (ks * 2 + (lane >> 4)) ^ (row & 3);
            ldsm_x4(af[im], sAb + row * 64 + c2 * 16);
        }
        uint32_t bf[8][2];
#pragma unroll
        for (int inp = 0; inp < 4; inp++) {
            int krow = ks * 16 + (lane & 15);
            uint32_t addr = sBb +
                swz128((uint32_t)(krow * 128 + inp * 32 + ((lane >> 4) << 4)));
            uint32_t r0, r1, r2, r3;
            ldsm_x4_t(r0, r1, r2, r3, addr);
            bf[inp * 2][0] = r0;     bf[inp * 2][1] = r1;
            bf[inp * 2 + 1][0] = r2; bf[inp * 2 + 1][1] = r3;
        }
#pragma unroll
        for (int im = 0; im < 2; im++)
#pragma unroll
            for (int in = 0; in < 8; in++)
                mma16816(acc[im][in], af[im], bf[in]);
    }

    // epilogue: scatter to g_y[m*4096 + r*128 + c*64 + n1] (fp16)
    const int g = lane >> 2, tq = lane & 3;
#pragma unroll
    for (int im = 0; im < 2; im++) {
#pragma unroll
        for (int half = 0; half < 2; half++) {
            int grow = bm * 128 + wid * 32 + im * 16 + g + half * 8;
            size_t ybase = (size_t)(grow >> 6) * 4096 + (grow & 63);
#pragma unroll
            for (int in = 0; in < 8; in++) {
#pragma unroll
                for (int e = 0; e < 2; e++) {
                    int j = in * 8 + tq * 2 + e;
                    int r = j & 31, c = j >> 5;
                    g_y[ybase + r * 128 + c * 64] =
                        __float2half(acc[im][in][half * 2 + e]);
                }
            }
        }
    }
}

// ---------------------------------------------------------------------------
// Stage 2: for each residue r: X_r = Yr[M,128] @ B2_r[128,72]
// grid (79 m-tiles, 32 r). CTA 128x72, 4 warps (warp 32x72). One-shot K=128.
// ---------------------------------------------------------------------------
#define S2_SMEM (32768 + 128 * 144)        // A 32KB + B 18KB = 50.2KB
__global__ __launch_bounds__(128)
void stage2_kernel(float* __restrict__ out) {
    extern __shared__ char smem[];
    const uint32_t sAb = (uint32_t)__cvta_generic_to_shared(smem);
    const uint32_t sBb = sAb + 32768;
    const int tid = threadIdx.x;
    const int wid = tid >> 5, lane = tid & 31;
    const int bm = blockIdx.x;
    const int rblk = blockIdx.y;

    // load A: 2048 x 16B  (rows = output rows m, cols = (c,n1) block at r)
#pragma unroll
    for (int q = 0; q < 16; q++) {
        int i = q * 128 + tid;
        int row = i >> 4, c16 = i & 15;
        int h = c16 >> 3, c8 = c16 & 7;
        int grow = bm * 128 + row;
        int gr = grow < M_ROWS ? grow : 0;
        cp16_pred(sAb + h * 16384 + swz128((uint32_t)(row * 128 + c8 * 16)),
                  &g_y[(size_t)gr * 4096 + rblk * 128 + c16 * 8],
                  grow < M_ROWS);
    }
    // load B: row per thread, 9 x 16B ; smem row stride 144B (self-conflict-free)
    {
        const __half* src = &g_b2[(size_t)rblk * 128 * S2_NB + tid * S2_NB];
#pragma unroll
        for (int cc = 0; cc < 9; cc++)
            cp16(sBb + tid * 144 + cc * 16, src + cc * 8);
    }
    cp_wait_all();
    __syncthreads();

    float acc[2][9][4];
#pragma unroll
    for (int a = 0; a < 2; a++)
#pragma unroll
        for (int bb = 0; bb < 9; bb++)
#pragma unroll
            for (int q = 0; q < 4; q++) acc[a][bb][q] = 0.0f;

#pragma unroll
    for (int ks = 0; ks < 8; ks++) {
        uint32_t af[2][4];
#pragma unroll
        for (int im = 0; im < 2; im++) {
            int row = wid * 32 + im * 16 + (lane & 15);
            int c16 = 2 * ks + (lane >> 4);
            int h = c16 >> 3, c8 = c16 & 7;
            ldsm_x4(af[im], sAb + h * 16384 +
                            swz128((uint32_t)(row * 128 + c8 * 16)));
        }
        uint32_t bf[9][2];
#pragma unroll
        for (int inp = 0; inp < 4; inp++) {
            int krow = ks * 16 + (lane & 15);
            uint32_t addr = sBb + krow * 144 + inp * 32 + ((lane >> 4) << 4);
            uint32_t r0, r1, r2, r3;
            ldsm_x4_t(r0, r1, r2, r3, addr);
            bf[inp * 2][0] = r0;     bf[inp * 2][1] = r1;
            bf[inp * 2 + 1][0] = r2; bf[inp * 2 + 1][1] = r3;
        }
        {
            int krow = ks * 16 + (lane & 15);
            ldsm_x2_t(bf[8][0], bf[8][1], sBb + krow * 144 + 128);
        }
#pragma unroll
        for (int im = 0; im < 2; im++)
#pragma unroll
            for (int in = 0; in < 9; in++)
                mma16816(acc[im][in], af[im], bf[in]);
    }

    // epilogue: j = 2*k2 + cout ; k = 32*k2 + rblk ; store real/imag halves
    const int g = lane >> 2, tq = lane & 3;
    const size_t imag_base = (size_t)M_ROWS * KFREQ;
#pragma unroll
    for (int im = 0; im < 2; im++) {
#pragma unroll
        for (int half = 0; half < 2; half++) {
            int row = bm * 128 + wid * 32 + im * 16 + g + half * 8;
            if (row >= M_ROWS) continue;
#pragma unroll
            for (int in = 0; in < 9; in++) {
#pragma unroll
                for (int e = 0; e < 2; e++) {
                    int j = in * 8 + tq * 2 + e;
                    if (j >= 66) continue;
                    int k = (j >> 1) * 32 + rblk;
                    if (k > 1024) continue;
                    size_t base = (j & 1) ? imag_base : 0;
                    out[base + (size_t)row * KFREQ + k] =
                        acc[im][in][half * 2 + e];
                }
            }
        }
    }
}

// ---------------------------------------------------------------------------
extern "C" void kernel_launch(void* const* d_in, const int* in_sizes, int n_in,
                              void* d_out, int out_size) {
    const float* x = (const float*)d_in[0];
    float* out = (float*)d_out;

    prep_b1_kernel<<<(32 * 64 + 255) / 256, 256>>>();
    prep_b2_kernel<<<(32 * 128 * S2_NB + 255) / 256, 256>>>();
    prep_a1_kernel<<<M_ROWS, 256>>>(x);
    stage1_kernel<<<M1 / 128, 128>>>();
    cudaFuncSetAttribute(stage2_kernel,
                         cudaFuncAttributeMaxDynamicSharedMemorySize, S2_SMEM);
    dim3 g2((M_ROWS + 127) / 128, 32);     // 79 x 32
    stage2_kernel<<<g2, 128, S2_SMEM>>>(out);
}

// round 6
// speedup vs baseline: 2.2754x; 1.8800x over previous
#include <cuda_runtime.h>
#include <cuda_fp16.h>
#include <cstdint>

// ---------------------------------------------------------------------------
// Problem constants
// ---------------------------------------------------------------------------
#define B_BATCH  16
#define L_LEN    320000
#define NFFT     2048
#define HOP      512
#define KFREQ    1025                     // N_FFT/2 + 1
#define T_FRAMES 626
#define M_ROWS   (B_BATCH * T_FRAMES)     // 10016
#define M_PAD    10112                    // 79 * 128
// Cooley-Tukey: n = n1 + 64*n2 ; Y[m,n1,r] = sum_n2 xw[n1+64n2] w32^{n2 r}
//                X[m,k] = sum_n1 Y[m,n1,k&31] * w2048^{n1 k}
#define S2_NB    72                       // padded stage-2 N (66 used)

// Scratch (__device__ globals — allocation-free rule)
__device__ __half g_y [(size_t)M_ROWS * 4096];        // ~82 MB [m][r][c][n1]
__device__ float  g_z [(size_t)32 * M_PAD * S2_NB];   // ~93 MB [r][m][j]
__device__ __half g_b1[32 * 64];                      // [n2][j] j<32:re else im
__device__ __half g_b2[32 * 128 * S2_NB];             // [r][kk][j]
__device__ float  g_win[NFFT];

// ---------------------------------------------------------------------------
// PTX helpers
// ---------------------------------------------------------------------------
__device__ __forceinline__ uint32_t swz128(uint32_t off) {
    return off ^ ((off >> 3) & 0x70);
}
__device__ __forceinline__ void cp16(uint32_t dst, const void* src) {
    asm volatile("cp.async.cg.shared.global [%0], [%1], 16;\n"
                 :: "r"(dst), "l"(src));
}
__device__ __forceinline__ void cp16_pred(uint32_t dst, const void* src, bool ok) {
    int sz = ok ? 16 : 0;
    asm volatile("cp.async.cg.shared.global [%0], [%1], 16, %2;\n"
                 :: "r"(dst), "l"(src), "r"(sz));
}
__device__ __forceinline__ void cp_wait_all() {
    asm volatile("cp.async.commit_group;\n" ::: "memory");
    asm volatile("cp.async.wait_group 0;\n" ::: "memory");
}
__device__ __forceinline__ void ldsm_x4(uint32_t* r, uint32_t addr) {
    asm volatile("ldmatrix.sync.aligned.m8n8.x4.shared.b16 {%0,%1,%2,%3}, [%4];\n"
                 : "=r"(r[0]), "=r"(r[1]), "=r"(r[2]), "=r"(r[3]) : "r"(addr));
}
__device__ __forceinline__ void ldsm_x4_t(uint32_t& r0, uint32_t& r1,
                                          uint32_t& r2, uint32_t& r3,
                                          uint32_t addr) {
    asm volatile("ldmatrix.sync.aligned.m8n8.x4.trans.shared.b16 {%0,%1,%2,%3}, [%4];\n"
                 : "=r"(r0), "=r"(r1), "=r"(r2), "=r"(r3) : "r"(addr));
}
__device__ __forceinline__ void ldsm_x2_t(uint32_t& r0, uint32_t& r1,
                                          uint32_t addr) {
    asm volatile("ldmatrix.sync.aligned.m8n8.x2.trans.shared.b16 {%0,%1}, [%2];\n"
                 : "=r"(r0), "=r"(r1) : "r"(addr));
}
__device__ __forceinline__ void mma16816(float* d, const uint32_t* a,
                                         const uint32_t* b) {
    asm volatile(
        "mma.sync.aligned.m16n8k16.row.col.f32.f16.f16.f32 "
        "{%0,%1,%2,%3}, {%4,%5,%6,%7}, {%8,%9}, {%0,%1,%2,%3};\n"
        : "+f"(d[0]), "+f"(d[1]), "+f"(d[2]), "+f"(d[3])
        : "r"(a[0]), "r"(a[1]), "r"(a[2]), "r"(a[3]), "r"(b[0]), "r"(b[1]));
}

// ---------------------------------------------------------------------------
// Tiny preps
// ---------------------------------------------------------------------------
__global__ void prep_win_kernel() {
    int i = blockIdx.x * blockDim.x + threadIdx.x;
    if (i < NFFT) g_win[i] = 0.5f - 0.5f * cospif((float)i / 1024.0f);
}
__global__ void prep_b1_kernel() {
    int i = blockIdx.x * blockDim.x + threadIdx.x;
    if (i >= 32 * 64) return;
    int n2 = i >> 6, j = i & 63;
    int r = j & 31;
    float s, c;
    sincospif((float)(n2 * r) / 16.0f, &s, &c);
    g_b1[i] = __float2half(j < 32 ? c : -s);
}
__global__ void prep_b2_kernel() {
    int i = blockIdx.x * blockDim.x + threadIdx.x;
    const int total = 32 * 128 * S2_NB;
    if (i >= total) return;
    int r   = i / (128 * S2_NB);
    int rem = i - r * (128 * S2_NB);
    int kk  = rem / S2_NB;
    int j   = rem - kk * S2_NB;
    float v = 0.0f;
    if (j < 66) {
        int n1 = kk & 63;
        int k  = (j >> 1) * 32 + r;
        float s, c;
        sincospif((float)(n1 * k) / 1024.0f, &s, &c);
        bool im_in  = kk >= 64;
        bool im_out = (j & 1) != 0;
        v = im_in ? (im_out ? c : s) : (im_out ? -s : c);
    }
    g_b2[i] = __float2half(v);
}

// ---------------------------------------------------------------------------
// Stage 1 (fused framing + DFT32 GEMM): one CTA = 4 frames (256 A-rows).
// smem: sA 16KB | sB 4KB | sRaw(32KB fp32, reused as sY 32KB fp16)
// Y written coalesced: 32KB contiguous per CTA.
// ---------------------------------------------------------------------------
#define S1_SMEM (16384 + 4096 + 32768)
__global__ __launch_bounds__(256)
void stage1_kernel(const float* __restrict__ x) {
    extern __shared__ char smem[];
    __half* sA   = (__half*)smem;                 // 256 x 32, 64B rows swizzled
    float*  sRaw = (float*)(smem + 20480);        // 4 x 2048 fp32
    __half* sY   = (__half*)(smem + 20480);       // 4 x 4096 fp16 (alias)
    const uint32_t sAb = (uint32_t)__cvta_generic_to_shared(smem);
    const uint32_t sBb = sAb + 16384;

    const int tid = threadIdx.x;
    const int wid = tid >> 5, lane = tid & 31;
    const int bm = blockIdx.x;

    // B1 -> smem (SW128)
    {
        int row = tid >> 3, c8 = tid & 7;
        uint4 v = *reinterpret_cast<const uint4*>(&g_b1[row * 64 + c8 * 8]);
        *reinterpret_cast<uint4*>(smem + 16384 +
            swz128((uint32_t)(row * 128 + c8 * 16))) = v;
    }
    // raw x frames -> smem (coalesced, reflect at edges)
#pragma unroll
    for (int f = 0; f < 4; f++) {
        int m = bm * 4 + f;
        int b = m / T_FRAMES;
        int tf = m - b * T_FRAMES;
        const float* xb = x + (size_t)b * L_LEN;
        int base = tf * HOP - 1024;
#pragma unroll
        for (int q = 0; q < 8; q++) {
            int p = q * 256 + tid;
            int jj = base + p;
            if (jj < 0)           jj = -jj;
            else if (jj >= L_LEN) jj = 2 * (L_LEN - 1) - jj;
            sRaw[f * 2048 + p] = xb[jj];
        }
    }
    __syncthreads();

    // window + transpose -> sA (thread = one A row (m_loc, n1))
    {
        int mloc = tid >> 6, n1 = tid & 63;
        const float* rp = sRaw + mloc * 2048;
#pragma unroll
        for (int c16 = 0; c16 < 4; c16++) {
            __half h[8];
#pragma unroll
            for (int e = 0; e < 8; e++) {
                int n = n1 + 64 * (c16 * 8 + e);
                h[e] = __float2half(rp[n] * g_win[n]);
            }
            int off = tid * 64 + ((c16 ^ (tid & 3)) << 4);
            *reinterpret_cast<uint4*>(smem + off) =
                *reinterpret_cast<uint4*>(h);
        }
    }
    __syncthreads();

    // mma: 8 warps, each 32 rows x 64 cols
    float acc[2][8][4];
#pragma unroll
    for (int a = 0; a < 2; a++)
#pragma unroll
        for (int bb = 0; bb < 8; bb++)
#pragma unroll
            for (int q = 0; q < 4; q++) acc[a][bb][q] = 0.0f;

#pragma unroll
    for (int ks = 0; ks < 2; ks++) {
        uint32_t af[2][4];
#pragma unroll
        for (int im = 0; im < 2; im++) {
            int row = wid * 32 + im * 16 + (lane & 15);
            int c2 = (ks * 2 + (lane >> 4)) ^ (row & 3);
            ldsm_x4(af[im], sAb + row * 64 + c2 * 16);
        }
        uint32_t bf[8][2];
#pragma unroll
        for (int inp = 0; inp < 4; inp++) {
            int krow = ks * 16 + (lane & 15);
            uint32_t addr = sBb +
                swz128((uint32_t)(krow * 128 + inp * 32 + ((lane >> 4) << 4)));
            uint32_t r0, r1, r2, r3;
            ldsm_x4_t(r0, r1, r2, r3, addr);
            bf[inp * 2][0] = r0;     bf[inp * 2][1] = r1;
            bf[inp * 2 + 1][0] = r2; bf[inp * 2 + 1][1] = r3;
        }
#pragma unroll
        for (int im = 0; im < 2; im++)
#pragma unroll
            for (int in = 0; in < 8; in++)
                mma16816(acc[im][in], af[im], bf[in]);
    }

    // transpose epilogue into sY [m_loc][r*128 + c*64 + n1]
    const int g = lane >> 2, tq = lane & 3;
#pragma unroll
    for (int im = 0; im < 2; im++) {
#pragma unroll
        for (int half = 0; half < 2; half++) {
            int row = wid * 32 + im * 16 + g + half * 8;
            int mloc = row >> 6, n1 = row & 63;
#pragma unroll
            for (int in = 0; in < 8; in++) {
#pragma unroll
                for (int e = 0; e < 2; e++) {
                    int j = in * 8 + tq * 2 + e;
                    sY[mloc * 4096 + (j & 31) * 128 + (j >> 5) * 64 + n1] =
                        __float2half(acc[im][in][half * 2 + e]);
                }
            }
        }
    }
    __syncthreads();

    // coalesced dump: 32KB contiguous
#pragma unroll
    for (int q = 0; q < 8; q++) {
        int ch = q * 256 + tid;
        *reinterpret_cast<uint4*>(&g_y[(size_t)bm * 16384 + ch * 8]) =
            reinterpret_cast<const uint4*>(sY)[ch];
    }
}

// ---------------------------------------------------------------------------
// Stage 2: per residue r: Z_r = Yr[M,128] @ B2_r[128,72] -> g_z coalesced
// grid (79, 32), CTA 128 thr, warp 32x72, one-shot K=128.
// ---------------------------------------------------------------------------
#define S2_SMEM (32768 + 128 * 144)
__global__ __launch_bounds__(128)
void stage2_kernel() {
    extern __shared__ char smem[];
    const uint32_t sAb = (uint32_t)__cvta_generic_to_shared(smem);
    const uint32_t sBb = sAb + 32768;
    const int tid = threadIdx.x;
    const int wid = tid >> 5, lane = tid & 31;
    const int bm = blockIdx.x;
    const int rblk = blockIdx.y;

#pragma unroll
    for (int q = 0; q < 16; q++) {
        int i = q * 128 + tid;
        int row = i >> 4, c16 = i & 15;
        int h = c16 >> 3, c8 = c16 & 7;
        int grow = bm * 128 + row;
        int gr = grow < M_ROWS ? grow : 0;
        cp16_pred(sAb + h * 16384 + swz128((uint32_t)(row * 128 + c8 * 16)),
                  &g_y[(size_t)gr * 4096 + rblk * 128 + c16 * 8],
                  grow < M_ROWS);
    }
    {
        const __half* src = &g_b2[(size_t)rblk * 128 * S2_NB + tid * S2_NB];
#pragma unroll
        for (int cc = 0; cc < 9; cc++)
            cp16(sBb + tid * 144 + cc * 16, src + cc * 8);
    }
    cp_wait_all();
    __syncthreads();

    float acc[2][9][4];
#pragma unroll
    for (int a = 0; a < 2; a++)
#pragma unroll
        for (int bb = 0; bb < 9; bb++)
#pragma unroll
            for (int q = 0; q < 4; q++) acc[a][bb][q] = 0.0f;

#pragma unroll
    for (int ks = 0; ks < 8; ks++) {
        uint32_t af[2][4];
#pragma unroll
        for (int im = 0; im < 2; im++) {
            int row = wid * 32 + im * 16 + (lane & 15);
            int c16 = 2 * ks + (lane >> 4);
            int h = c16 >> 3, c8 = c16 & 7;
            ldsm_x4(af[im], sAb + h * 16384 +
                            swz128((uint32_t)(row * 128 + c8 * 16)));
        }
        uint32_t bf[9][2];
#pragma unroll
        for (int inp = 0; inp < 4; inp++) {
            int krow = ks * 16 + (lane & 15);
            uint32_t addr = sBb + krow * 144 + inp * 32 + ((lane >> 4) << 4);
            uint32_t r0, r1, r2, r3;
            ldsm_x4_t(r0, r1, r2, r3, addr);
            bf[inp * 2][0] = r0;     bf[inp * 2][1] = r1;
            bf[inp * 2 + 1][0] = r2; bf[inp * 2 + 1][1] = r3;
        }
        {
            int krow = ks * 16 + (lane & 15);
            ldsm_x2_t(bf[8][0], bf[8][1], sBb + krow * 144 + 128);
        }
#pragma unroll
        for (int im = 0; im < 2; im++)
#pragma unroll
            for (int in = 0; in < 9; in++)
                mma16816(acc[im][in], af[im], bf[in]);
    }

    // coalesced float2 stores to g_z[rblk][grow][j]
    const int g = lane >> 2, tq = lane & 3;
#pragma unroll
    for (int im = 0; im < 2; im++) {
#pragma unroll
        for (int half = 0; half < 2; half++) {
            int grow = bm * 128 + wid * 32 + im * 16 + g + half * 8;
            float* dst = &g_z[((size_t)rblk * M_PAD + grow) * S2_NB];
#pragma unroll
            for (int in = 0; in < 9; in++) {
                int j0 = in * 8 + tq * 2;
                *reinterpret_cast<float2*>(dst + j0) =
                    make_float2(acc[im][in][half * 2],
                                acc[im][in][half * 2 + 1]);
            }
        }
    }
}

// ---------------------------------------------------------------------------
// Reorder: g_z[r][m][j] -> out (real/imag planes), fully coalesced both sides.
// CTA = 8 output rows; smem slices padded to 577 floats (bank-safe).
// ---------------------------------------------------------------------------
#define RB      8
#define SLICE   577                              // 8*72 + 1 (odd)
#define RD_SMEM (32 * SLICE * 4)                 // 73856 B
__global__ __launch_bounds__(256)
void reorder_kernel(float* __restrict__ out) {
    extern __shared__ float s[];
    const int tid = threadIdx.x;
    const int m0 = blockIdx.x * RB;

    // load 32 slices x (8 x 72) floats, coalesced float4
#pragma unroll
    for (int q = 0; q < 18; q++) {
        int ch = q * 256 + tid;                  // 4608 chunks
        int r = ch / 144, w = ch - r * 144;
        float4 v = *reinterpret_cast<const float4*>(
            &g_z[((size_t)r * M_PAD + m0) * S2_NB + w * 4]);
        float* dst = &s[r * SLICE + w * 4];
        dst[0] = v.x; dst[1] = v.y; dst[2] = v.z; dst[3] = v.w;
    }
    __syncthreads();

    const size_t imag_base = (size_t)M_ROWS * KFREQ;
#pragma unroll 4
    for (int q = 0; q < 65; q++) {
        int o = q * 256 + tid;
        if (o < RB * 2050) {
            int mm = o / 2050;
            int rem = o - mm * 2050;
            int cout = rem / 1025;
            int k = rem - cout * 1025;
            int r = k & 31, k2 = k >> 5;
            float v = s[r * SLICE + mm * S2_NB + 2 * k2 + cout];
            out[(cout ? imag_base : 0) + (size_t)(m0 + mm) * KFREQ + k] = v;
        }
    }
}

// ---------------------------------------------------------------------------
extern "C" void kernel_launch(void* const* d_in, const int* in_sizes, int n_in,
                              void* d_out, int out_size) {
    const float* x = (const float*)d_in[0];
    float* out = (float*)d_out;

    cudaFuncSetAttribute(stage1_kernel,
                         cudaFuncAttributeMaxDynamicSharedMemorySize, S1_SMEM);
    cudaFuncSetAttribute(stage2_kernel,
                         cudaFuncAttributeMaxDynamicSharedMemorySize, S2_SMEM);
    cudaFuncSetAttribute(reorder_kernel,
                         cudaFuncAttributeMaxDynamicSharedMemorySize, RD_SMEM);

    prep_win_kernel<<<8, 256>>>();
    prep_b1_kernel<<<8, 256>>>();
    prep_b2_kernel<<<(32 * 128 * S2_NB + 255) / 256, 256>>>();

    stage1_kernel<<<M_ROWS / 4, 256, S1_SMEM>>>(x);

    dim3 g2((M_ROWS + 127) / 128, 32);           // 79 x 32
    stage2_kernel<<<g2, 128, S2_SMEM>>>();

    reorder_kernel<<<M_ROWS / RB, 256, RD_SMEM>>>(out);
}